// round 3
// baseline (speedup 1.0000x reference)
#include <cuda_runtime.h>
#include <cuda_bf16.h>
#include <math.h>

#define H_F 38
#define W_F 50
#define C_F 512
#define CROP_SZ 14
#define ROI 7
#define NPROP 1000
#define D_FLAT (ROI*ROI*C_F)   // 25088
#define D_HID 4096
#define N_CLS 21
#define N_REG 80

// Scratch (no allocations allowed anywhere)
__device__ float g_pooled[(size_t)NPROP * D_FLAT];
__device__ float g_h1[(size_t)NPROP * D_HID];
__device__ float g_h2[(size_t)NPROP * D_HID];

// ---------------------------------------------------------------------------
// Kernel 1: crop_and_resize (TF semantics, 14x14) + 2x2 maxpool -> pooled[n,7,7,512]
// One block per proposal, 256 threads.
// ---------------------------------------------------------------------------
__global__ void roi_pool_kernel(const float* __restrict__ feats,
                                const float* __restrict__ props,
                                float* __restrict__ pooled) {
    const int n = blockIdx.x;
    __shared__ int   sy0[CROP_SZ], sy1[CROP_SZ], sx0[CROP_SZ], sx1[CROP_SZ];
    __shared__ float swy[CROP_SZ], swx[CROP_SZ];
    const int tid = threadIdx.x;

    if (tid < CROP_SZ) {
        const float y1 = props[n * 4 + 0];
        const float y2 = props[n * 4 + 2];
        float ys = y1 * (float)(H_F - 1)
                 + (float)tid * ((y2 - y1) * (float)(H_F - 1) / (float)(CROP_SZ - 1));
        float y0f = floorf(ys);
        int y0 = min(max((int)y0f, 0), H_F - 1);
        sy0[tid] = y0;
        sy1[tid] = min(y0 + 1, H_F - 1);
        swy[tid] = ys - y0f;
    } else if (tid >= 32 && tid < 32 + CROP_SZ) {
        const int i = tid - 32;
        const float x1 = props[n * 4 + 1];
        const float x2 = props[n * 4 + 3];
        float xs = x1 * (float)(W_F - 1)
                 + (float)i * ((x2 - x1) * (float)(W_F - 1) / (float)(CROP_SZ - 1));
        float x0f = floorf(xs);
        int x0 = min(max((int)x0f, 0), W_F - 1);
        sx0[i] = x0;
        sx1[i] = min(x0 + 1, W_F - 1);
        swx[i] = xs - x0f;
    }
    __syncthreads();

    for (int out = tid; out < D_FLAT; out += blockDim.x) {
        const int c  = out & (C_F - 1);
        const int pw = (out >> 9) % ROI;
        const int ph = out / (C_F * ROI);
        float m = -1e30f;
        #pragma unroll
        for (int sy = 0; sy < 2; sy++) {
            const int iy = 2 * ph + sy;
            const int y0 = sy0[iy], y1i = sy1[iy];
            const float wy = swy[iy];
            #pragma unroll
            for (int sx = 0; sx < 2; sx++) {
                const int ix = 2 * pw + sx;
                const int x0 = sx0[ix], x1i = sx1[ix];
                const float wx = swx[ix];
                const float v00 = feats[((size_t)(y0  * W_F + x0 ) * C_F) + c];
                const float v01 = feats[((size_t)(y0  * W_F + x1i) * C_F) + c];
                const float v10 = feats[((size_t)(y1i * W_F + x0 ) * C_F) + c];
                const float v11 = feats[((size_t)(y1i * W_F + x1i) * C_F) + c];
                const float top = v00 * (1.0f - wx) + v01 * wx;
                const float bot = v10 * (1.0f - wx) + v11 * wx;
                const float v   = top * (1.0f - wy) + bot * wy;
                m = fmaxf(m, v);
            }
        }
        pooled[(size_t)n * D_FLAT + out] = m;
    }
}

// ---------------------------------------------------------------------------
// Kernel 2: C[N,M] = relu?(A[N,K] @ B[K,M] + bias[M])
// Classic 128x128x8 SGEMM, 256 threads, 8x8 per thread.
// ---------------------------------------------------------------------------
template <bool RELU>
__global__ void __launch_bounds__(256)
sgemm_bias_kernel(const float* __restrict__ A,
                  const float* __restrict__ B,
                  const float* __restrict__ bias,
                  float* __restrict__ C,
                  int N, int M, int K) {
    constexpr int BM = 128, BN = 128, BK = 8, TM = 8, TN = 8;
    __shared__ float As[BK][BM];
    __shared__ float Bs[BK][BN];

    const int tid = threadIdx.x;
    const int rowBase = blockIdx.y * BM;
    const int colBase = blockIdx.x * BN;

    const int aRow = tid >> 1;          // 0..127
    const int aCol = (tid & 1) * 4;     // 0 or 4
    const int bRow = tid >> 5;          // 0..7
    const int bCol = (tid & 31) * 4;    // 0..124

    const int threadRow = (tid >> 4) * TM;  // 0..120
    const int threadCol = (tid & 15) * TN;  // 0..120

    float acc[TM][TN];
    #pragma unroll
    for (int i = 0; i < TM; i++)
        #pragma unroll
        for (int j = 0; j < TN; j++) acc[i][j] = 0.0f;

    const float* Aptr = A + (size_t)rowBase * K;
    const float* Bptr = B + colBase;
    const bool aValid = (rowBase + aRow) < N;

    for (int k0 = 0; k0 < K; k0 += BK) {
        float4 av = make_float4(0.f, 0.f, 0.f, 0.f);
        if (aValid)
            av = *(const float4*)(Aptr + (size_t)aRow * K + k0 + aCol);
        As[aCol + 0][aRow] = av.x;
        As[aCol + 1][aRow] = av.y;
        As[aCol + 2][aRow] = av.z;
        As[aCol + 3][aRow] = av.w;

        float4 bv = *(const float4*)(Bptr + (size_t)(k0 + bRow) * M + bCol);
        *(float4*)&Bs[bRow][bCol] = bv;
        __syncthreads();

        #pragma unroll
        for (int k = 0; k < BK; k++) {
            float ar[TM], br[TN];
            #pragma unroll
            for (int i = 0; i < TM; i++) ar[i] = As[k][threadRow + i];
            #pragma unroll
            for (int j = 0; j < TN; j++) br[j] = Bs[k][threadCol + j];
            #pragma unroll
            for (int i = 0; i < TM; i++)
                #pragma unroll
                for (int j = 0; j < TN; j++)
                    acc[i][j] += ar[i] * br[j];
        }
        __syncthreads();
    }

    #pragma unroll
    for (int i = 0; i < TM; i++) {
        const int r = rowBase + threadRow + i;
        if (r >= N) break;
        #pragma unroll
        for (int j = 0; j < TN; j++) {
            const int cidx = colBase + threadCol + j;
            float v = acc[i][j] + bias[cidx];
            if (RELU) v = fmaxf(v, 0.0f);
            C[(size_t)r * M + cidx] = v;
        }
    }
}

// ---------------------------------------------------------------------------
// Kernel 3: heads. One block per row. cls = softmax(x@Wc+bc), reg = x@Wr+br.
// out layout: [0, 21000) cls row-major, [21000, 101000) reg row-major.
// ---------------------------------------------------------------------------
__global__ void __launch_bounds__(128)
heads_kernel(const float* __restrict__ X,
             const float* __restrict__ Wc, const float* __restrict__ bc,
             const float* __restrict__ Wr, const float* __restrict__ br,
             float* __restrict__ out) {
    const int n = blockIdx.x;
    __shared__ float xrow[D_HID];
    __shared__ float head[N_CLS + N_REG];
    const int tid = threadIdx.x;

    for (int k = tid; k < D_HID; k += 128)
        xrow[k] = X[(size_t)n * D_HID + k];
    __syncthreads();

    const int warp = tid >> 5;
    const int lane = tid & 31;
    for (int o = warp; o < N_CLS + N_REG; o += 4) {
        float sum = 0.0f;
        float bval;
        if (o < N_CLS) {
            for (int k = lane; k < D_HID; k += 32)
                sum += xrow[k] * Wc[(size_t)k * N_CLS + o];
            bval = bc[o];
        } else {
            const int j = o - N_CLS;
            for (int k = lane; k < D_HID; k += 32)
                sum += xrow[k] * Wr[(size_t)k * N_REG + j];
            bval = br[j];
        }
        #pragma unroll
        for (int off = 16; off > 0; off >>= 1)
            sum += __shfl_down_sync(0xffffffffu, sum, off);
        if (lane == 0) head[o] = sum + bval;
    }
    __syncthreads();

    if (tid == 0) {
        float mx = head[0];
        #pragma unroll
        for (int o = 1; o < N_CLS; o++) mx = fmaxf(mx, head[o]);
        float s = 0.0f;
        float e[N_CLS];
        #pragma unroll
        for (int o = 0; o < N_CLS; o++) { e[o] = expf(head[o] - mx); s += e[o]; }
        const float inv = 1.0f / s;
        #pragma unroll
        for (int o = 0; o < N_CLS; o++)
            out[(size_t)n * N_CLS + o] = e[o] * inv;
    }
    if (tid >= 32 && tid < 32 + N_REG) {
        const int j = tid - 32;
        out[(size_t)NPROP * N_CLS + (size_t)n * N_REG + j] = head[N_CLS + j];
    }
}

// ---------------------------------------------------------------------------
extern "C" void kernel_launch(void* const* d_in, const int* in_sizes, int n_in,
                              void* d_out, int out_size) {
    const float* feats = (const float*)d_in[0];
    const float* props = (const float*)d_in[1];
    const float* W1    = (const float*)d_in[2];
    const float* b1    = (const float*)d_in[3];
    const float* W2    = (const float*)d_in[4];
    const float* b2    = (const float*)d_in[5];
    const float* Wc    = (const float*)d_in[6];
    const float* bc    = (const float*)d_in[7];
    const float* Wr    = (const float*)d_in[8];
    const float* br    = (const float*)d_in[9];
    float* out = (float*)d_out;

    float *pooled, *h1, *h2;
    cudaGetSymbolAddress((void**)&pooled, g_pooled);
    cudaGetSymbolAddress((void**)&h1, g_h1);
    cudaGetSymbolAddress((void**)&h2, g_h2);

    // 1) ROI align + maxpool
    roi_pool_kernel<<<NPROP, 256>>>(feats, props, pooled);

    // 2) FC1: [1000, 25088] x [25088, 4096] + b1, relu
    {
        dim3 grid(D_HID / 128, (NPROP + 127) / 128);
        sgemm_bias_kernel<true><<<grid, 256>>>(pooled, W1, b1, h1, NPROP, D_HID, D_FLAT);
    }
    // 3) FC2: [1000, 4096] x [4096, 4096] + b2, relu
    {
        dim3 grid(D_HID / 128, (NPROP + 127) / 128);
        sgemm_bias_kernel<true><<<grid, 256>>>(h1, W2, b2, h2, NPROP, D_HID, D_HID);
    }
    // 4) heads: cls softmax + reg
    heads_kernel<<<NPROP, 128>>>(h2, Wc, bc, Wr, br, out);
}

// round 8
// speedup vs baseline: 1.6657x; 1.6657x over previous
#include <cuda_runtime.h>
#include <cuda_bf16.h>
#include <math.h>
#include <stdint.h>

#define H_F 38
#define W_F 50
#define C_F 512
#define CROP_SZ 14
#define ROI 7
#define NPROP 1000
#define MPAD 1024
#define K1 25088
#define DH 4096
#define N_CLS 21
#define N_REG 80

// ---------------- scratch (static device globals; no allocation APIs) -------
// A-side layout per row: [hi(K) | lo(K)]  (row stride = 2K elements)
__device__ __nv_bfloat16 g_A3[(size_t)MPAD * 2 * K1];  // split pooled features
__device__ __nv_bfloat16 g_B1[(size_t)DH * 2 * K1];    // W1^T split
__device__ __nv_bfloat16 g_H3[(size_t)MPAD * 2 * DH];  // FC1 out split
__device__ __nv_bfloat16 g_B2[(size_t)DH * 2 * DH];    // W2^T split
__device__ float         g_h2[(size_t)MPAD * DH];      // FC2 out fp32 (padded rows)

// ---------------- PTX helpers (all plain sm_80+ features, no 'a' needed) ----
__device__ __forceinline__ uint32_t smem_u32(const void* p) {
    uint32_t a;
    asm("{ .reg .u64 t; cvta.to.shared.u64 t, %1; cvt.u32.u64 %0, t; }"
        : "=r"(a) : "l"(p));
    return a;
}
__device__ __forceinline__ void cp16(uint32_t dst, const void* src) {
    asm volatile("cp.async.cg.shared.global [%0], [%1], 16;"
                 :: "r"(dst), "l"(src) : "memory");
}
__device__ __forceinline__ void ldsm4(uint32_t* r, uint32_t a) {
    asm volatile("ldmatrix.sync.aligned.m8n8.x4.shared.b16 {%0,%1,%2,%3}, [%4];"
                 : "=r"(r[0]), "=r"(r[1]), "=r"(r[2]), "=r"(r[3]) : "r"(a));
}
__device__ __forceinline__ void mma_bf16(float* c, const uint32_t* a,
                                         uint32_t b0, uint32_t b1) {
    asm volatile(
        "mma.sync.aligned.m16n8k16.row.col.f32.bf16.bf16.f32 "
        "{%0,%1,%2,%3}, {%4,%5,%6,%7}, {%8,%9}, {%0,%1,%2,%3};"
        : "+f"(c[0]), "+f"(c[1]), "+f"(c[2]), "+f"(c[3])
        : "r"(a[0]), "r"(a[1]), "r"(a[2]), "r"(a[3]), "r"(b0), "r"(b1));
}

// ---------------------------------------------------------------------------
// Kernel 1: crop_and_resize + 2x2 maxpool, fused bf16 hi/lo split into g_A3.
// Blocks NPROP..MPAD-1 zero the pad rows (deterministic every launch).
// ---------------------------------------------------------------------------
__global__ void roi_pool_kernel(const float* __restrict__ feats,
                                const float* __restrict__ props) {
    const int n = blockIdx.x;
    const int tid = threadIdx.x;

    if (n >= NPROP) {  // zero pad rows
        uint4 z = make_uint4(0u, 0u, 0u, 0u);
        uint4* row = (uint4*)(g_A3 + (size_t)n * 2 * K1);
        for (int i = tid; i < (2 * K1) / 8; i += blockDim.x) row[i] = z;
        return;
    }

    __shared__ int   sy0[CROP_SZ], sy1[CROP_SZ], sx0[CROP_SZ], sx1[CROP_SZ];
    __shared__ float swy[CROP_SZ], swx[CROP_SZ];

    if (tid < CROP_SZ) {
        const float y1 = props[n * 4 + 0];
        const float y2 = props[n * 4 + 2];
        float ys = y1 * (float)(H_F - 1)
                 + (float)tid * ((y2 - y1) * (float)(H_F - 1) / (float)(CROP_SZ - 1));
        float y0f = floorf(ys);
        int y0 = min(max((int)y0f, 0), H_F - 1);
        sy0[tid] = y0;
        sy1[tid] = min(y0 + 1, H_F - 1);
        swy[tid] = ys - y0f;
    } else if (tid >= 32 && tid < 32 + CROP_SZ) {
        const int i = tid - 32;
        const float x1 = props[n * 4 + 1];
        const float x2 = props[n * 4 + 3];
        float xs = x1 * (float)(W_F - 1)
                 + (float)i * ((x2 - x1) * (float)(W_F - 1) / (float)(CROP_SZ - 1));
        float x0f = floorf(xs);
        int x0 = min(max((int)x0f, 0), W_F - 1);
        sx0[i] = x0;
        sx1[i] = min(x0 + 1, W_F - 1);
        swx[i] = xs - x0f;
    }
    __syncthreads();

    for (int out = tid; out < K1; out += blockDim.x) {
        const int c  = out & (C_F - 1);
        const int pw = (out >> 9) % ROI;
        const int ph = out / (C_F * ROI);
        float m = -1e30f;
        #pragma unroll
        for (int sy = 0; sy < 2; sy++) {
            const int iy = 2 * ph + sy;
            const int y0 = sy0[iy], y1i = sy1[iy];
            const float wy = swy[iy];
            #pragma unroll
            for (int sx = 0; sx < 2; sx++) {
                const int ix = 2 * pw + sx;
                const int x0 = sx0[ix], x1i = sx1[ix];
                const float wx = swx[ix];
                const float v00 = feats[((size_t)(y0  * W_F + x0 ) * C_F) + c];
                const float v01 = feats[((size_t)(y0  * W_F + x1i) * C_F) + c];
                const float v10 = feats[((size_t)(y1i * W_F + x0 ) * C_F) + c];
                const float v11 = feats[((size_t)(y1i * W_F + x1i) * C_F) + c];
                const float top = v00 * (1.0f - wx) + v01 * wx;
                const float bot = v10 * (1.0f - wx) + v11 * wx;
                const float v   = top * (1.0f - wy) + bot * wy;
                m = fmaxf(m, v);
            }
        }
        __nv_bfloat16 hi = __float2bfloat16(m);
        __nv_bfloat16 lo = __float2bfloat16(m - __bfloat162float(hi));
        const size_t base = (size_t)n * 2 * K1;
        g_A3[base + out]      = hi;
        g_A3[base + K1 + out] = lo;
    }
}

// ---------------------------------------------------------------------------
// Kernel 2: transpose + bf16 split of weights: W[K,N] fp32 -> B[N, 2K] bf16
// per row n: [0,K)=hi, [K,2K)=lo
// ---------------------------------------------------------------------------
__global__ void __launch_bounds__(256)
w_transpose_split(const float* __restrict__ W, __nv_bfloat16* __restrict__ B3,
                  int K, int N) {
    __shared__ float t[32][33];
    const int k0 = blockIdx.y * 32, n0 = blockIdx.x * 32;
    const int tx = threadIdx.x, ty = threadIdx.y;   // 32 x 8
    #pragma unroll
    for (int i = 0; i < 4; i++) {
        int k = k0 + ty + i * 8;
        t[ty + i * 8][tx] = W[(size_t)k * N + n0 + tx];
    }
    __syncthreads();
    #pragma unroll
    for (int i = 0; i < 4; i++) {
        int n = n0 + ty + i * 8;
        int k = k0 + tx;
        float v = t[tx][ty + i * 8];
        __nv_bfloat16 hi = __float2bfloat16(v);
        __nv_bfloat16 lo = __float2bfloat16(v - __bfloat162float(hi));
        size_t base = (size_t)n * 2 * (size_t)K;
        B3[base + k]     = hi;
        B3[base + K + k] = lo;
    }
}

// ---------------------------------------------------------------------------
// Kernel 3: warp-level mma.sync bf16 GEMM with 3-term split accumulation.
// C = relu(Ah*Bh + Al*Bh + Ah*Bl + bias). BM=BN=128, BK=32 per term.
// 256 threads = 2x4 warps, 64x32 per warp, m16n8k16 fragments.
// MODE 1: re-split output to g_H3. MODE 2: fp32 output to g_h2.
// ---------------------------------------------------------------------------
#define TILE_B   10240            // 128 rows * 80 bytes (32 k-elems + 8 pad)
#define STAGE_B  (4 * TILE_B)     // Ah, Al, Bh, Bl
#define GEMM_SMEM (2 * STAGE_B)   // 81920

template <int MODE>
__global__ void __launch_bounds__(256, 1)
gemm_mma(const __nv_bfloat16* __restrict__ A, const __nv_bfloat16* __restrict__ B,
         const float* __restrict__ bias, int K) {
    extern __shared__ char smem[];
    const uint32_t sb = smem_u32(smem);
    const int tid = threadIdx.x;
    const int lane = tid & 31, wid = tid >> 5;
    const int warp_m = wid >> 2, warp_n = wid & 3;
    const int rowBase = blockIdx.y * 128, colBase = blockIdx.x * 128;
    const int nIter = K >> 5;

    // global->smem: thread t loads 32B (2x16B) per tile; row = t/2, half = t&1
    const int lr = tid >> 1, lh = tid & 1;
    const size_t strideA = 2 * (size_t)K;
    const __nv_bfloat16* aSrc = A + (size_t)(rowBase + lr) * strideA + lh * 16;
    const __nv_bfloat16* bSrc = B + (size_t)(colBase + lr) * strideA + lh * 16;
    const uint32_t dBase = sb + lr * 80 + lh * 32;

    auto issue = [&](int it) {
        const uint32_t d = dBase + (uint32_t)((it & 1) * STAGE_B);
        const __nv_bfloat16* ap = aSrc + (size_t)it * 32;
        const __nv_bfloat16* bp = bSrc + (size_t)it * 32;
        cp16(d,                    ap);          // Ah
        cp16(d + 16,               ap + 8);
        cp16(d + TILE_B,           ap + K);      // Al
        cp16(d + TILE_B + 16,      ap + K + 8);
        cp16(d + 2 * TILE_B,       bp);          // Bh
        cp16(d + 2 * TILE_B + 16,  bp + 8);
        cp16(d + 3 * TILE_B,       bp + K);      // Bl
        cp16(d + 3 * TILE_B + 16,  bp + K + 8);
        asm volatile("cp.async.commit_group;" ::: "memory");
    };

    float acc[4][4][4];
    #pragma unroll
    for (int i = 0; i < 4; i++)
        #pragma unroll
        for (int j = 0; j < 4; j++)
            #pragma unroll
            for (int q = 0; q < 4; q++) acc[i][j][q] = 0.0f;

    issue(0);

    // ldmatrix base addresses (row-major tiles, 80B row stride)
    const uint32_t aLM = sb + (uint32_t)((warp_m * 64 + (lane & 15)) * 80 + (lane >> 4) * 16);
    const uint32_t bLM = sb + 2 * TILE_B
                       + (uint32_t)((warp_n * 32 + (lane & 15)) * 80 + (lane >> 4) * 16);

    for (int it = 0; it < nIter; ++it) {
        if (it + 1 < nIter) {
            issue(it + 1);
            asm volatile("cp.async.wait_group 1;" ::: "memory");
        } else {
            asm volatile("cp.async.wait_group 0;" ::: "memory");
        }
        __syncthreads();

        const uint32_t so = (uint32_t)((it & 1) * STAGE_B);
        #pragma unroll
        for (int ks = 0; ks < 2; ++ks) {
            const uint32_t kb = ks * 32;   // 16 k-elems = 32 bytes
            uint32_t ah[4][4], bh[2][4];
            #pragma unroll
            for (int mt = 0; mt < 4; mt++) ldsm4(ah[mt], aLM + so + mt * 1280 + kb);
            #pragma unroll
            for (int p = 0; p < 2; p++)    ldsm4(bh[p], bLM + so + p * 1280 + kb);
            #pragma unroll
            for (int mt = 0; mt < 4; mt++)
                #pragma unroll
                for (int nt = 0; nt < 4; nt++)
                    mma_bf16(acc[mt][nt], ah[mt],
                             bh[nt >> 1][nt & 1], bh[nt >> 1][2 + (nt & 1)]);
            {
                uint32_t al[4][4];
                #pragma unroll
                for (int mt = 0; mt < 4; mt++)
                    ldsm4(al[mt], aLM + so + TILE_B + mt * 1280 + kb);
                #pragma unroll
                for (int mt = 0; mt < 4; mt++)
                    #pragma unroll
                    for (int nt = 0; nt < 4; nt++)
                        mma_bf16(acc[mt][nt], al[mt],
                                 bh[nt >> 1][nt & 1], bh[nt >> 1][2 + (nt & 1)]);
            }
            {
                uint32_t bl[2][4];
                #pragma unroll
                for (int p = 0; p < 2; p++)
                    ldsm4(bl[p], bLM + so + TILE_B + p * 1280 + kb);
                #pragma unroll
                for (int mt = 0; mt < 4; mt++)
                    #pragma unroll
                    for (int nt = 0; nt < 4; nt++)
                        mma_bf16(acc[mt][nt], ah[mt],
                                 bl[nt >> 1][nt & 1], bl[nt >> 1][2 + (nt & 1)]);
            }
        }
        __syncthreads();
    }

    // Epilogue: bias + relu, direct global writes.
    // Frag layout m16n8: c0/c1 -> row lane/4, cols (lane%4)*2 + {0,1}; c2/c3 -> row+8.
    const int r0 = rowBase + warp_m * 64 + (lane >> 2);
    const int c0 = colBase + warp_n * 32 + (lane & 3) * 2;
    #pragma unroll
    for (int mt = 0; mt < 4; mt++) {
        #pragma unroll
        for (int nt = 0; nt < 4; nt++) {
            const int r = r0 + mt * 16;
            const int c = c0 + nt * 8;
            const float bv0 = __ldg(bias + c);
            const float bv1 = __ldg(bias + c + 1);
            float v00 = fmaxf(acc[mt][nt][0] + bv0, 0.0f);
            float v01 = fmaxf(acc[mt][nt][1] + bv1, 0.0f);
            float v10 = fmaxf(acc[mt][nt][2] + bv0, 0.0f);
            float v11 = fmaxf(acc[mt][nt][3] + bv1, 0.0f);
            if (MODE == 1) {
                #pragma unroll
                for (int rr = 0; rr < 2; rr++) {
                    float a = rr ? v10 : v00;
                    float b = rr ? v11 : v01;
                    __nv_bfloat16 h0 = __float2bfloat16(a);
                    __nv_bfloat16 l0 = __float2bfloat16(a - __bfloat162float(h0));
                    __nv_bfloat16 h1 = __float2bfloat16(b);
                    __nv_bfloat16 l1 = __float2bfloat16(b - __bfloat162float(h1));
                    __nv_bfloat16* rp = g_H3 + (size_t)(r + rr * 8) * 2 * DH + c;
                    *(__nv_bfloat162*)rp        = __nv_bfloat162(h0, h1);
                    *(__nv_bfloat162*)(rp + DH) = __nv_bfloat162(l0, l1);
                }
            } else {
                *(float2*)&g_h2[(size_t)r * DH + c]       = make_float2(v00, v01);
                *(float2*)&g_h2[(size_t)(r + 8) * DH + c] = make_float2(v10, v11);
            }
        }
    }
}

// ---------------------------------------------------------------------------
// Kernel 4: heads. cls softmax (21) + reg (80). out = [cls | reg].
// ---------------------------------------------------------------------------
__global__ void __launch_bounds__(128)
heads_kernel(const float* __restrict__ X,
             const float* __restrict__ Wc, const float* __restrict__ bc,
             const float* __restrict__ Wr, const float* __restrict__ br,
             float* __restrict__ out) {
    const int n = blockIdx.x;
    __shared__ float xrow[DH];
    __shared__ float head[N_CLS + N_REG];
    const int tid = threadIdx.x;

    for (int k = tid; k < DH; k += 128)
        xrow[k] = X[(size_t)n * DH + k];
    __syncthreads();

    const int warp = tid >> 5;
    const int lane = tid & 31;
    for (int o = warp; o < N_CLS + N_REG; o += 4) {
        float sum = 0.0f;
        float bval;
        if (o < N_CLS) {
            for (int k = lane; k < DH; k += 32)
                sum += xrow[k] * Wc[(size_t)k * N_CLS + o];
            bval = bc[o];
        } else {
            const int j = o - N_CLS;
            for (int k = lane; k < DH; k += 32)
                sum += xrow[k] * Wr[(size_t)k * N_REG + j];
            bval = br[j];
        }
        #pragma unroll
        for (int off = 16; off > 0; off >>= 1)
            sum += __shfl_down_sync(0xffffffffu, sum, off);
        if (lane == 0) head[o] = sum + bval;
    }
    __syncthreads();

    if (tid == 0) {
        float mx = head[0];
        #pragma unroll
        for (int o = 1; o < N_CLS; o++) mx = fmaxf(mx, head[o]);
        float s = 0.0f;
        float e[N_CLS];
        #pragma unroll
        for (int o = 0; o < N_CLS; o++) { e[o] = expf(head[o] - mx); s += e[o]; }
        const float inv = 1.0f / s;
        #pragma unroll
        for (int o = 0; o < N_CLS; o++)
            out[(size_t)n * N_CLS + o] = e[o] * inv;
    }
    if (tid >= 32 && tid < 32 + N_REG) {
        const int j = tid - 32;
        out[(size_t)NPROP * N_CLS + (size_t)n * N_REG + j] = head[N_CLS + j];
    }
}

// ---------------------------------------------------------------------------
extern "C" void kernel_launch(void* const* d_in, const int* in_sizes, int n_in,
                              void* d_out, int out_size) {
    const float* feats = (const float*)d_in[0];
    const float* props = (const float*)d_in[1];
    const float* W1    = (const float*)d_in[2];
    const float* b1    = (const float*)d_in[3];
    const float* W2    = (const float*)d_in[4];
    const float* b2    = (const float*)d_in[5];
    const float* Wc    = (const float*)d_in[6];
    const float* bc    = (const float*)d_in[7];
    const float* Wr    = (const float*)d_in[8];
    const float* br    = (const float*)d_in[9];
    float* out = (float*)d_out;

    __nv_bfloat16 *A3, *B1, *H3, *B2;
    float* h2;
    cudaGetSymbolAddress((void**)&A3, g_A3);
    cudaGetSymbolAddress((void**)&B1, g_B1);
    cudaGetSymbolAddress((void**)&H3, g_H3);
    cudaGetSymbolAddress((void**)&B2, g_B2);
    cudaGetSymbolAddress((void**)&h2, g_h2);

    cudaFuncSetAttribute(gemm_mma<1>, cudaFuncAttributeMaxDynamicSharedMemorySize, GEMM_SMEM);
    cudaFuncSetAttribute(gemm_mma<2>, cudaFuncAttributeMaxDynamicSharedMemorySize, GEMM_SMEM);

    // 1) ROI align + maxpool + bf16 split (+ zero pad rows)
    roi_pool_kernel<<<MPAD, 256>>>(feats, props);

    // 2) weight transpose + split
    w_transpose_split<<<dim3(DH / 32, K1 / 32), dim3(32, 8)>>>(W1, B1, K1, DH);
    w_transpose_split<<<dim3(DH / 32, DH / 32), dim3(32, 8)>>>(W2, B2, DH, DH);

    // 3) FC1: [1024, K1] x [4096, K1]^T (3-term split), bias+relu, split out
    gemm_mma<1><<<dim3(DH / 128, MPAD / 128), 256, GEMM_SMEM>>>(A3, B1, b1, K1);

    // 4) FC2: [1024, DH] x [4096, DH]^T (3-term split), bias+relu, fp32 out
    gemm_mma<2><<<dim3(DH / 128, MPAD / 128), 256, GEMM_SMEM>>>(H3, B2, b2, DH);

    // 5) heads
    heads_kernel<<<NPROP, 128>>>(h2, Wc, bc, Wr, br, out);
}

// round 13
// speedup vs baseline: 1.7027x; 1.0222x over previous
#include <cuda_runtime.h>
#include <cuda_bf16.h>
#include <math.h>
#include <stdint.h>

#define H_F 38
#define W_F 50
#define C_F 512
#define CROP_SZ 14
#define ROI 7
#define NPROP 1000
#define MPAD 1024
#define K1 25088
#define DH 4096
#define N_CLS 21
#define N_REG 80
#define N_HEAD (N_CLS + N_REG)   // 101

// ---------------- scratch (static device globals; no allocation APIs) -------
// A-side layout per row: [hi(K) | lo(K)]  (row stride = 2K elements)
__device__ __nv_bfloat16 g_A3[(size_t)MPAD * 2 * K1];  // split pooled features
__device__ __nv_bfloat16 g_B1[(size_t)DH * 2 * K1];    // W1^T split
__device__ __nv_bfloat16 g_H3[(size_t)MPAD * 2 * DH];  // FC1 out split
__device__ __nv_bfloat16 g_B2[(size_t)DH * 2 * DH];    // W2^T split
__device__ float         g_h2[(size_t)MPAD * DH];      // FC2 out fp32

// ---------------- PTX helpers (plain sm_80+ features only) ------------------
__device__ __forceinline__ uint32_t smem_u32(const void* p) {
    uint32_t a;
    asm("{ .reg .u64 t; cvta.to.shared.u64 t, %1; cvt.u32.u64 %0, t; }"
        : "=r"(a) : "l"(p));
    return a;
}
__device__ __forceinline__ void cp16(uint32_t dst, const void* src) {
    asm volatile("cp.async.cg.shared.global [%0], [%1], 16;"
                 :: "r"(dst), "l"(src) : "memory");
}
__device__ __forceinline__ void ldsm4(uint32_t* r, uint32_t a) {
    asm volatile("ldmatrix.sync.aligned.m8n8.x4.shared.b16 {%0,%1,%2,%3}, [%4];"
                 : "=r"(r[0]), "=r"(r[1]), "=r"(r[2]), "=r"(r[3]) : "r"(a));
}
__device__ __forceinline__ void mma_bf16(float* c, const uint32_t* a,
                                         uint32_t b0, uint32_t b1) {
    asm volatile(
        "mma.sync.aligned.m16n8k16.row.col.f32.bf16.bf16.f32 "
        "{%0,%1,%2,%3}, {%4,%5,%6,%7}, {%8,%9}, {%0,%1,%2,%3};"
        : "+f"(c[0]), "+f"(c[1]), "+f"(c[2]), "+f"(c[3])
        : "r"(a[0]), "r"(a[1]), "r"(a[2]), "r"(a[3]), "r"(b0), "r"(b1));
}

// ---------------------------------------------------------------------------
// Kernel 1: crop_and_resize + 2x2 maxpool, fused bf16 hi/lo split into g_A3.
// ---------------------------------------------------------------------------
__global__ void roi_pool_kernel(const float* __restrict__ feats,
                                const float* __restrict__ props) {
    const int n = blockIdx.x;
    const int tid = threadIdx.x;

    if (n >= NPROP) {  // zero pad rows (deterministic every launch)
        uint4 z = make_uint4(0u, 0u, 0u, 0u);
        uint4* row = (uint4*)(g_A3 + (size_t)n * 2 * K1);
        for (int i = tid; i < (2 * K1) / 8; i += blockDim.x) row[i] = z;
        return;
    }

    __shared__ int   sy0[CROP_SZ], sy1[CROP_SZ], sx0[CROP_SZ], sx1[CROP_SZ];
    __shared__ float swy[CROP_SZ], swx[CROP_SZ];

    if (tid < CROP_SZ) {
        const float y1 = props[n * 4 + 0];
        const float y2 = props[n * 4 + 2];
        float ys = y1 * (float)(H_F - 1)
                 + (float)tid * ((y2 - y1) * (float)(H_F - 1) / (float)(CROP_SZ - 1));
        float y0f = floorf(ys);
        int y0 = min(max((int)y0f, 0), H_F - 1);
        sy0[tid] = y0;
        sy1[tid] = min(y0 + 1, H_F - 1);
        swy[tid] = ys - y0f;
    } else if (tid >= 32 && tid < 32 + CROP_SZ) {
        const int i = tid - 32;
        const float x1 = props[n * 4 + 1];
        const float x2 = props[n * 4 + 3];
        float xs = x1 * (float)(W_F - 1)
                 + (float)i * ((x2 - x1) * (float)(W_F - 1) / (float)(CROP_SZ - 1));
        float x0f = floorf(xs);
        int x0 = min(max((int)x0f, 0), W_F - 1);
        sx0[i] = x0;
        sx1[i] = min(x0 + 1, W_F - 1);
        swx[i] = xs - x0f;
    }
    __syncthreads();

    for (int out = tid; out < K1; out += blockDim.x) {
        const int c  = out & (C_F - 1);
        const int pw = (out >> 9) % ROI;
        const int ph = out / (C_F * ROI);
        float m = -1e30f;
        #pragma unroll
        for (int sy = 0; sy < 2; sy++) {
            const int iy = 2 * ph + sy;
            const int y0 = sy0[iy], y1i = sy1[iy];
            const float wy = swy[iy];
            #pragma unroll
            for (int sx = 0; sx < 2; sx++) {
                const int ix = 2 * pw + sx;
                const int x0 = sx0[ix], x1i = sx1[ix];
                const float wx = swx[ix];
                const float v00 = feats[((size_t)(y0  * W_F + x0 ) * C_F) + c];
                const float v01 = feats[((size_t)(y0  * W_F + x1i) * C_F) + c];
                const float v10 = feats[((size_t)(y1i * W_F + x0 ) * C_F) + c];
                const float v11 = feats[((size_t)(y1i * W_F + x1i) * C_F) + c];
                const float top = v00 * (1.0f - wx) + v01 * wx;
                const float bot = v10 * (1.0f - wx) + v11 * wx;
                const float v   = top * (1.0f - wy) + bot * wy;
                m = fmaxf(m, v);
            }
        }
        __nv_bfloat16 hi = __float2bfloat16(m);
        __nv_bfloat16 lo = __float2bfloat16(m - __bfloat162float(hi));
        const size_t base = (size_t)n * 2 * K1;
        g_A3[base + out]      = hi;
        g_A3[base + K1 + out] = lo;
    }
}

// ---------------------------------------------------------------------------
// Kernel 2: transpose + bf16 split of weights: W[K,N] fp32 -> B[N, 2K] bf16
// ---------------------------------------------------------------------------
__global__ void __launch_bounds__(256)
w_transpose_split(const float* __restrict__ W, __nv_bfloat16* __restrict__ B3,
                  int K, int N) {
    __shared__ float t[32][33];
    const int k0 = blockIdx.y * 32, n0 = blockIdx.x * 32;
    const int tx = threadIdx.x, ty = threadIdx.y;   // 32 x 8
    #pragma unroll
    for (int i = 0; i < 4; i++) {
        int k = k0 + ty + i * 8;
        t[ty + i * 8][tx] = W[(size_t)k * N + n0 + tx];
    }
    __syncthreads();
    #pragma unroll
    for (int i = 0; i < 4; i++) {
        int n = n0 + ty + i * 8;
        int k = k0 + tx;
        float v = t[tx][ty + i * 8];
        __nv_bfloat16 hi = __float2bfloat16(v);
        __nv_bfloat16 lo = __float2bfloat16(v - __bfloat162float(hi));
        size_t base = (size_t)n * 2 * (size_t)K;
        B3[base + k]     = hi;
        B3[base + K + k] = lo;
    }
}

// ---------------------------------------------------------------------------
// Kernel 3: warp-level mma.sync bf16 GEMM, 3-term split accumulation.
// BM=BN=128, BK=32. 3-stage cp.async pipeline, ONE syncthreads per chunk.
// SMEM: XOR-swizzled 64B rows; 4 tiles (Ah,Al,Bh,Bl) x 8KB; stage=32KB; 96KB.
// ---------------------------------------------------------------------------
#define TILE_B   8192
#define STAGE_B  32768
#define GEMM_SMEM (3 * STAGE_B)   // 98304

template <int MODE>
__global__ void __launch_bounds__(256, 1)
gemm_mma(const __nv_bfloat16* __restrict__ A, const __nv_bfloat16* __restrict__ B,
         const float* __restrict__ bias, int K) {
    extern __shared__ char smem[];
    const uint32_t sb = smem_u32(smem);
    const int tid = threadIdx.x;
    const int lane = tid & 31, wid = tid >> 5;
    const int warp_m = wid >> 2, warp_n = wid & 3;
    const int rowBase = blockIdx.y * 128, colBase = blockIdx.x * 128;
    const int nIter = K >> 5;

    // ---- global->smem mapping: thread = (row, 32B-half); swizzled dst ----
    const int lr = tid >> 1, lh = tid & 1;
    const size_t strideA = 2 * (size_t)K;
    const __nv_bfloat16* aSrc = A + (size_t)(rowBase + lr) * strideA + lh * 16;
    const __nv_bfloat16* bSrc = B + (size_t)(colBase + lr) * strideA + lh * 16;
    const uint32_t xw = (uint32_t)(lr & 3) << 4;
    const uint32_t d0off = (uint32_t)lr * 64 + (((uint32_t)(2 * lh)     << 4) ^ xw);
    const uint32_t d1off = (uint32_t)lr * 64 + (((uint32_t)(2 * lh + 1) << 4) ^ xw);

    auto issue = [&](int it, int slot) {
        const uint32_t d = sb + (uint32_t)slot * STAGE_B;
        const __nv_bfloat16* ap = aSrc + (size_t)it * 32;
        const __nv_bfloat16* bp = bSrc + (size_t)it * 32;
        cp16(d + d0off,              ap);          // Ah
        cp16(d + d1off,              ap + 8);
        cp16(d + TILE_B + d0off,     ap + K);      // Al
        cp16(d + TILE_B + d1off,     ap + K + 8);
        cp16(d + 2 * TILE_B + d0off, bp);          // Bh
        cp16(d + 2 * TILE_B + d1off, bp + 8);
        cp16(d + 3 * TILE_B + d0off, bp + K);      // Bl
        cp16(d + 3 * TILE_B + d1off, bp + K + 8);
        asm volatile("cp.async.commit_group;" ::: "memory");
    };

    float acc[4][4][4];
    #pragma unroll
    for (int i = 0; i < 4; i++)
        #pragma unroll
        for (int j = 0; j < 4; j++)
            #pragma unroll
            for (int q = 0; q < 4; q++) acc[i][j][q] = 0.0f;

    issue(0, 0);
    issue(1, 1);

    // ---- ldmatrix addressing (swizzled) ----
    const int rA = warp_m * 64 + (lane & 15);
    const int rB = warp_n * 32 + (lane & 15);
    const uint32_t xA = (uint32_t)(rA & 3) << 4;
    const uint32_t xB = (uint32_t)(rB & 3) << 4;
    const uint32_t aBase = sb + (uint32_t)rA * 64;
    const uint32_t bBase = sb + 2 * TILE_B + (uint32_t)rB * 64;
    const uint32_t cl = (uint32_t)(lane >> 4);   // 0/1: which 16B chunk of the k16

    int sp = 2;   // next issue slot
    int sc = 0;   // current compute slot

    for (int it = 0; it < nIter; ++it) {
        if (it + 1 < nIter) {
            asm volatile("cp.async.wait_group 1;" ::: "memory");
        } else {
            asm volatile("cp.async.wait_group 0;" ::: "memory");
        }
        __syncthreads();

        if (it + 2 < nIter) {
            issue(it + 2, sp);
            sp = (sp == 2) ? 0 : sp + 1;
        }

        const uint32_t so = (uint32_t)sc * STAGE_B;
        #pragma unroll
        for (int ks = 0; ks < 2; ++ks) {
            const uint32_t cByte = (uint32_t)(2 * ks + cl) << 4;
            const uint32_t cA = cByte ^ xA;
            const uint32_t cB = cByte ^ xB;
            uint32_t ah[4][4], bh[2][4];
            #pragma unroll
            for (int mt = 0; mt < 4; mt++) ldsm4(ah[mt], aBase + so + mt * 1024 + cA);
            #pragma unroll
            for (int p = 0; p < 2; p++)    ldsm4(bh[p], bBase + so + p * 1024 + cB);
            #pragma unroll
            for (int mt = 0; mt < 4; mt++)
                #pragma unroll
                for (int nt = 0; nt < 4; nt++)
                    mma_bf16(acc[mt][nt], ah[mt],
                             bh[nt >> 1][nt & 1], bh[nt >> 1][2 + (nt & 1)]);
            {
                uint32_t al[4][4];
                #pragma unroll
                for (int mt = 0; mt < 4; mt++)
                    ldsm4(al[mt], aBase + so + TILE_B + mt * 1024 + cA);
                #pragma unroll
                for (int mt = 0; mt < 4; mt++)
                    #pragma unroll
                    for (int nt = 0; nt < 4; nt++)
                        mma_bf16(acc[mt][nt], al[mt],
                                 bh[nt >> 1][nt & 1], bh[nt >> 1][2 + (nt & 1)]);
            }
            {
                uint32_t bl[2][4];
                #pragma unroll
                for (int p = 0; p < 2; p++)
                    ldsm4(bl[p], bBase + so + TILE_B + p * 1024 + cB);
                #pragma unroll
                for (int mt = 0; mt < 4; mt++)
                    #pragma unroll
                    for (int nt = 0; nt < 4; nt++)
                        mma_bf16(acc[mt][nt], ah[mt],
                                 bl[nt >> 1][nt & 1], bl[nt >> 1][2 + (nt & 1)]);
            }
        }
        sc = (sc == 2) ? 0 : sc + 1;
    }

    // ---- Epilogue: bias + relu, direct global writes (no smem use) ----
    const int r0 = rowBase + warp_m * 64 + (lane >> 2);
    const int c0 = colBase + warp_n * 32 + (lane & 3) * 2;
    #pragma unroll
    for (int mt = 0; mt < 4; mt++) {
        #pragma unroll
        for (int nt = 0; nt < 4; nt++) {
            const int r = r0 + mt * 16;
            const int c = c0 + nt * 8;
            const float bv0 = __ldg(bias + c);
            const float bv1 = __ldg(bias + c + 1);
            float v00 = fmaxf(acc[mt][nt][0] + bv0, 0.0f);
            float v01 = fmaxf(acc[mt][nt][1] + bv1, 0.0f);
            float v10 = fmaxf(acc[mt][nt][2] + bv0, 0.0f);
            float v11 = fmaxf(acc[mt][nt][3] + bv1, 0.0f);
            if (MODE == 1) {
                #pragma unroll
                for (int rr = 0; rr < 2; rr++) {
                    float a = rr ? v10 : v00;
                    float b = rr ? v11 : v01;
                    __nv_bfloat16 h0 = __float2bfloat16(a);
                    __nv_bfloat16 l0 = __float2bfloat16(a - __bfloat162float(h0));
                    __nv_bfloat16 h1 = __float2bfloat16(b);
                    __nv_bfloat16 l1 = __float2bfloat16(b - __bfloat162float(h1));
                    __nv_bfloat16* rp = g_H3 + (size_t)(r + rr * 8) * 2 * DH + c;
                    *(__nv_bfloat162*)rp        = __nv_bfloat162(h0, h1);
                    *(__nv_bfloat162*)(rp + DH) = __nv_bfloat162(l0, l1);
                }
            } else {
                *(float2*)&g_h2[(size_t)r * DH + c]       = make_float2(v00, v01);
                *(float2*)&g_h2[(size_t)(r + 8) * DH + c] = make_float2(v10, v11);
            }
        }
    }
}

// ---------------------------------------------------------------------------
// Kernel 4: heads, 8 rows per block (amortize head-weight reads 8x).
// cls softmax (21) + reg (80). out = [cls | reg].
// ---------------------------------------------------------------------------
#define XR 4104                       // padded row stride (conflict-free)
#define HEADS_SMEM ((8 * XR + N_HEAD * 8) * 4)

__global__ void __launch_bounds__(256)
heads8_kernel(const float* __restrict__ X,
              const float* __restrict__ Wc, const float* __restrict__ bc,
              const float* __restrict__ Wr, const float* __restrict__ br,
              float* __restrict__ out) {
    extern __shared__ float hs[];
    float* xs = hs;                   // [8][XR]
    float* hv = hs + 8 * XR;          // [N_HEAD][8]
    const int n0 = blockIdx.x * 8;
    const int tid = threadIdx.x;
    const int wid = tid >> 5, lane = tid & 31;

    for (int i = tid; i < 8 * DH; i += 256) {
        const int r = i >> 12, k = i & (DH - 1);
        xs[r * XR + k] = X[(size_t)(n0 + r) * DH + k];
    }
    __syncthreads();

    for (int o = wid; o < N_HEAD; o += 8) {
        const float* Wp;
        int ld;
        float bv;
        if (o < N_CLS) { Wp = Wc + o;           ld = N_CLS; bv = bc[o]; }
        else           { Wp = Wr + (o - N_CLS); ld = N_REG; bv = br[o - N_CLS]; }
        float a0=0,a1=0,a2=0,a3=0,a4=0,a5=0,a6=0,a7=0;
        for (int k = lane; k < DH; k += 32) {
            const float w = __ldg(Wp + (size_t)k * ld);
            a0 += xs[0*XR + k] * w;  a1 += xs[1*XR + k] * w;
            a2 += xs[2*XR + k] * w;  a3 += xs[3*XR + k] * w;
            a4 += xs[4*XR + k] * w;  a5 += xs[5*XR + k] * w;
            a6 += xs[6*XR + k] * w;  a7 += xs[7*XR + k] * w;
        }
        #pragma unroll
        for (int off = 16; off > 0; off >>= 1) {
            a0 += __shfl_down_sync(0xffffffffu, a0, off);
            a1 += __shfl_down_sync(0xffffffffu, a1, off);
            a2 += __shfl_down_sync(0xffffffffu, a2, off);
            a3 += __shfl_down_sync(0xffffffffu, a3, off);
            a4 += __shfl_down_sync(0xffffffffu, a4, off);
            a5 += __shfl_down_sync(0xffffffffu, a5, off);
            a6 += __shfl_down_sync(0xffffffffu, a6, off);
            a7 += __shfl_down_sync(0xffffffffu, a7, off);
        }
        if (lane == 0) {
            hv[o * 8 + 0] = a0 + bv;  hv[o * 8 + 1] = a1 + bv;
            hv[o * 8 + 2] = a2 + bv;  hv[o * 8 + 3] = a3 + bv;
            hv[o * 8 + 4] = a4 + bv;  hv[o * 8 + 5] = a5 + bv;
            hv[o * 8 + 6] = a6 + bv;  hv[o * 8 + 7] = a7 + bv;
        }
    }
    __syncthreads();

    if (tid < 8) {
        const int r = tid;
        float mx = hv[r];
        #pragma unroll
        for (int o = 1; o < N_CLS; o++) mx = fmaxf(mx, hv[o * 8 + r]);
        float s = 0.0f;
        float e[N_CLS];
        #pragma unroll
        for (int o = 0; o < N_CLS; o++) { e[o] = expf(hv[o * 8 + r] - mx); s += e[o]; }
        const float inv = 1.0f / s;
        #pragma unroll
        for (int o = 0; o < N_CLS; o++)
            out[(size_t)(n0 + r) * N_CLS + o] = e[o] * inv;
    }
    for (int i = tid; i < 8 * N_REG; i += 256) {
        const int r = i / N_REG, j = i - r * N_REG;
        out[(size_t)NPROP * N_CLS + (size_t)(n0 + r) * N_REG + j] = hv[(N_CLS + j) * 8 + r];
    }
}

// ---------------------------------------------------------------------------
extern "C" void kernel_launch(void* const* d_in, const int* in_sizes, int n_in,
                              void* d_out, int out_size) {
    const float* feats = (const float*)d_in[0];
    const float* props = (const float*)d_in[1];
    const float* W1    = (const float*)d_in[2];
    const float* b1    = (const float*)d_in[3];
    const float* W2    = (const float*)d_in[4];
    const float* b2    = (const float*)d_in[5];
    const float* Wc    = (const float*)d_in[6];
    const float* bc    = (const float*)d_in[7];
    const float* Wr    = (const float*)d_in[8];
    const float* br    = (const float*)d_in[9];
    float* out = (float*)d_out;

    __nv_bfloat16 *A3, *B1, *H3, *B2;
    float* h2;
    cudaGetSymbolAddress((void**)&A3, g_A3);
    cudaGetSymbolAddress((void**)&B1, g_B1);
    cudaGetSymbolAddress((void**)&H3, g_H3);
    cudaGetSymbolAddress((void**)&B2, g_B2);
    cudaGetSymbolAddress((void**)&h2, g_h2);

    cudaFuncSetAttribute(gemm_mma<1>, cudaFuncAttributeMaxDynamicSharedMemorySize, GEMM_SMEM);
    cudaFuncSetAttribute(gemm_mma<2>, cudaFuncAttributeMaxDynamicSharedMemorySize, GEMM_SMEM);
    cudaFuncSetAttribute(heads8_kernel, cudaFuncAttributeMaxDynamicSharedMemorySize, HEADS_SMEM);

    // 1) ROI align + maxpool + bf16 split (+ zero pad rows)
    roi_pool_kernel<<<MPAD, 256>>>(feats, props);

    // 2) weight transpose + split
    w_transpose_split<<<dim3(DH / 32, K1 / 32), dim3(32, 8)>>>(W1, B1, K1, DH);
    w_transpose_split<<<dim3(DH / 32, DH / 32), dim3(32, 8)>>>(W2, B2, DH, DH);

    // 3) FC1: [1024, K1] x [4096, K1]^T (3-term split), bias+relu, split out
    gemm_mma<1><<<dim3(DH / 128, MPAD / 128), 256, GEMM_SMEM>>>(A3, B1, b1, K1);

    // 4) FC2: [1024, DH] x [4096, DH]^T (3-term split), bias+relu, fp32 out
    gemm_mma<2><<<dim3(DH / 128, MPAD / 128), 256, GEMM_SMEM>>>(H3, B2, b2, DH);

    // 5) heads (8 rows per block)
    heads8_kernel<<<NPROP / 8, 256, HEADS_SMEM>>>(h2, Wc, bc, Wr, br, out);
}

// round 16
// speedup vs baseline: 2.9369x; 1.7248x over previous
#include <cuda_runtime.h>
#include <cuda_bf16.h>
#include <math.h>
#include <stdint.h>

#define H_F 38
#define W_F 50
#define C_F 512
#define CROP_SZ 14
#define ROI 7
#define NPROP 1000
#define MPAD 1024
#define K1 25088
#define DH 4096
#define N_CLS 21
#define N_REG 80
#define N_HEAD (N_CLS + N_REG)   // 101

// ---------------- scratch (static device globals; no allocation APIs) -------
// A-side layout per row: [hi(K) | lo(K)]  (row stride = 2K elements)
__device__ __nv_bfloat16 g_A3[(size_t)MPAD * 2 * K1];  // split pooled features
__device__ __nv_bfloat16 g_B1[(size_t)DH * 2 * K1];    // W1^T split
__device__ __nv_bfloat16 g_H3[(size_t)MPAD * 2 * DH];  // FC1 out split
__device__ __nv_bfloat16 g_B2[(size_t)DH * 2 * DH];    // W2^T split
__device__ float         g_h2[(size_t)MPAD * DH];      // FC2 out fp32

// ---------------- PTX helpers (plain sm_80+ features only) ------------------
__device__ __forceinline__ uint32_t smem_u32(const void* p) {
    uint32_t a;
    asm("{ .reg .u64 t; cvta.to.shared.u64 t, %1; cvt.u32.u64 %0, t; }"
        : "=r"(a) : "l"(p));
    return a;
}
__device__ __forceinline__ void cp16(uint32_t dst, const void* src) {
    asm volatile("cp.async.cg.shared.global [%0], [%1], 16;"
                 :: "r"(dst), "l"(src) : "memory");
}
__device__ __forceinline__ void ldsm4(uint32_t* r, uint32_t a) {
    asm volatile("ldmatrix.sync.aligned.m8n8.x4.shared.b16 {%0,%1,%2,%3}, [%4];"
                 : "=r"(r[0]), "=r"(r[1]), "=r"(r[2]), "=r"(r[3]) : "r"(a));
}
__device__ __forceinline__ void mma_bf16(float* c, const uint32_t* a,
                                         uint32_t b0, uint32_t b1) {
    asm volatile(
        "mma.sync.aligned.m16n8k16.row.col.f32.bf16.bf16.f32 "
        "{%0,%1,%2,%3}, {%4,%5,%6,%7}, {%8,%9}, {%0,%1,%2,%3};"
        : "+f"(c[0]), "+f"(c[1]), "+f"(c[2]), "+f"(c[3])
        : "r"(a[0]), "r"(a[1]), "r"(a[2]), "r"(a[3]), "r"(b0), "r"(b1));
}

// ---------------------------------------------------------------------------
// Kernel 1: crop_and_resize + 2x2 maxpool, fused bf16 hi/lo split into g_A3.
// ---------------------------------------------------------------------------
__global__ void roi_pool_kernel(const float* __restrict__ feats,
                                const float* __restrict__ props) {
    const int n = blockIdx.x;
    const int tid = threadIdx.x;

    if (n >= NPROP) {  // zero pad rows (deterministic every launch)
        uint4 z = make_uint4(0u, 0u, 0u, 0u);
        uint4* row = (uint4*)(g_A3 + (size_t)n * 2 * K1);
        for (int i = tid; i < (2 * K1) / 8; i += blockDim.x) row[i] = z;
        return;
    }

    __shared__ int   sy0[CROP_SZ], sy1[CROP_SZ], sx0[CROP_SZ], sx1[CROP_SZ];
    __shared__ float swy[CROP_SZ], swx[CROP_SZ];

    if (tid < CROP_SZ) {
        const float y1 = props[n * 4 + 0];
        const float y2 = props[n * 4 + 2];
        float ys = y1 * (float)(H_F - 1)
                 + (float)tid * ((y2 - y1) * (float)(H_F - 1) / (float)(CROP_SZ - 1));
        float y0f = floorf(ys);
        int y0 = min(max((int)y0f, 0), H_F - 1);
        sy0[tid] = y0;
        sy1[tid] = min(y0 + 1, H_F - 1);
        swy[tid] = ys - y0f;
    } else if (tid >= 32 && tid < 32 + CROP_SZ) {
        const int i = tid - 32;
        const float x1 = props[n * 4 + 1];
        const float x2 = props[n * 4 + 3];
        float xs = x1 * (float)(W_F - 1)
                 + (float)i * ((x2 - x1) * (float)(W_F - 1) / (float)(CROP_SZ - 1));
        float x0f = floorf(xs);
        int x0 = min(max((int)x0f, 0), W_F - 1);
        sx0[i] = x0;
        sx1[i] = min(x0 + 1, W_F - 1);
        swx[i] = xs - x0f;
    }
    __syncthreads();

    for (int out = tid; out < K1; out += blockDim.x) {
        const int c  = out & (C_F - 1);
        const int pw = (out >> 9) % ROI;
        const int ph = out / (C_F * ROI);
        float m = -1e30f;
        #pragma unroll
        for (int sy = 0; sy < 2; sy++) {
            const int iy = 2 * ph + sy;
            const int y0 = sy0[iy], y1i = sy1[iy];
            const float wy = swy[iy];
            #pragma unroll
            for (int sx = 0; sx < 2; sx++) {
                const int ix = 2 * pw + sx;
                const int x0 = sx0[ix], x1i = sx1[ix];
                const float wx = swx[ix];
                const float v00 = feats[((size_t)(y0  * W_F + x0 ) * C_F) + c];
                const float v01 = feats[((size_t)(y0  * W_F + x1i) * C_F) + c];
                const float v10 = feats[((size_t)(y1i * W_F + x0 ) * C_F) + c];
                const float v11 = feats[((size_t)(y1i * W_F + x1i) * C_F) + c];
                const float top = v00 * (1.0f - wx) + v01 * wx;
                const float bot = v10 * (1.0f - wx) + v11 * wx;
                const float v   = top * (1.0f - wy) + bot * wy;
                m = fmaxf(m, v);
            }
        }
        __nv_bfloat16 hi = __float2bfloat16(m);
        __nv_bfloat16 lo = __float2bfloat16(m - __bfloat162float(hi));
        const size_t base = (size_t)n * 2 * K1;
        g_A3[base + out]      = hi;
        g_A3[base + K1 + out] = lo;
    }
}

// ---------------------------------------------------------------------------
// Kernel 2: transpose + bf16 split of weights: W[K,N] fp32 -> B[N, 2K] bf16
// ---------------------------------------------------------------------------
__global__ void __launch_bounds__(256)
w_transpose_split(const float* __restrict__ W, __nv_bfloat16* __restrict__ B3,
                  int K, int N) {
    __shared__ float t[32][33];
    const int k0 = blockIdx.y * 32, n0 = blockIdx.x * 32;
    const int tx = threadIdx.x, ty = threadIdx.y;   // 32 x 8
    #pragma unroll
    for (int i = 0; i < 4; i++) {
        int k = k0 + ty + i * 8;
        t[ty + i * 8][tx] = W[(size_t)k * N + n0 + tx];
    }
    __syncthreads();
    #pragma unroll
    for (int i = 0; i < 4; i++) {
        int n = n0 + ty + i * 8;
        int k = k0 + tx;
        float v = t[tx][ty + i * 8];
        __nv_bfloat16 hi = __float2bfloat16(v);
        __nv_bfloat16 lo = __float2bfloat16(v - __bfloat162float(hi));
        size_t base = (size_t)n * 2 * (size_t)K;
        B3[base + k]     = hi;
        B3[base + K + k] = lo;
    }
}

// ---------------------------------------------------------------------------
// Kernel 3: warp-level mma.sync bf16 GEMM, 3-term split accumulation.
// BM=BN=128, BK=32. 3-stage cp.async pipeline, ONE syncthreads per chunk.
// Term order ah*bh -> ah*bl -> al*bh with register reuse (al overwrites ah)
// to stay under 128 regs => 2 CTAs/SM (the round-13 occupancy fix).
// ---------------------------------------------------------------------------
#define TILE_B   8192
#define STAGE_B  32768
#define GEMM_SMEM (3 * STAGE_B)   // 98304

template <int MODE>
__global__ void __launch_bounds__(256, 2)
gemm_mma(const __nv_bfloat16* __restrict__ A, const __nv_bfloat16* __restrict__ B,
         const float* __restrict__ bias, int K) {
    extern __shared__ char smem[];
    const uint32_t sb = smem_u32(smem);
    const int tid = threadIdx.x;
    const int lane = tid & 31, wid = tid >> 5;
    const int warp_m = wid >> 2, warp_n = wid & 3;
    const int rowBase = blockIdx.y * 128, colBase = blockIdx.x * 128;
    const int nIter = K >> 5;

    // ---- global->smem mapping: thread = (row, 32B-half); swizzled dst ----
    const int lr = tid >> 1, lh = tid & 1;
    const size_t strideA = 2 * (size_t)K;
    const __nv_bfloat16* aSrc = A + (size_t)(rowBase + lr) * strideA + lh * 16;
    const __nv_bfloat16* bSrc = B + (size_t)(colBase + lr) * strideA + lh * 16;
    const uint32_t xw = (uint32_t)(lr & 3) << 4;
    const uint32_t d0off = (uint32_t)lr * 64 + (((uint32_t)(2 * lh)     << 4) ^ xw);
    const uint32_t d1off = (uint32_t)lr * 64 + (((uint32_t)(2 * lh + 1) << 4) ^ xw);

    auto issue = [&](int it, int slot) {
        const uint32_t d = sb + (uint32_t)slot * STAGE_B;
        const __nv_bfloat16* ap = aSrc + (size_t)it * 32;
        const __nv_bfloat16* bp = bSrc + (size_t)it * 32;
        cp16(d + d0off,              ap);          // Ah
        cp16(d + d1off,              ap + 8);
        cp16(d + TILE_B + d0off,     ap + K);      // Al
        cp16(d + TILE_B + d1off,     ap + K + 8);
        cp16(d + 2 * TILE_B + d0off, bp);          // Bh
        cp16(d + 2 * TILE_B + d1off, bp + 8);
        cp16(d + 3 * TILE_B + d0off, bp + K);      // Bl
        cp16(d + 3 * TILE_B + d1off, bp + K + 8);
        asm volatile("cp.async.commit_group;" ::: "memory");
    };

    float acc[4][4][4];
    #pragma unroll
    for (int i = 0; i < 4; i++)
        #pragma unroll
        for (int j = 0; j < 4; j++)
            #pragma unroll
            for (int q = 0; q < 4; q++) acc[i][j][q] = 0.0f;

    issue(0, 0);
    issue(1, 1);

    // ---- ldmatrix addressing (swizzled) ----
    const int rA = warp_m * 64 + (lane & 15);
    const int rB = warp_n * 32 + (lane & 15);
    const uint32_t xA = (uint32_t)(rA & 3) << 4;
    const uint32_t xB = (uint32_t)(rB & 3) << 4;
    const uint32_t aBase = sb + (uint32_t)rA * 64;
    const uint32_t bBase = sb + 2 * TILE_B + (uint32_t)rB * 64;
    const uint32_t cl = (uint32_t)(lane >> 4);   // 0/1: which 16B chunk of the k16

    int sp = 2;   // next issue slot
    int sc = 0;   // current compute slot

    for (int it = 0; it < nIter; ++it) {
        if (it + 1 < nIter) {
            asm volatile("cp.async.wait_group 1;" ::: "memory");
        } else {
            asm volatile("cp.async.wait_group 0;" ::: "memory");
        }
        __syncthreads();

        if (it + 2 < nIter) {
            issue(it + 2, sp);
            sp = (sp == 2) ? 0 : sp + 1;
        }

        const uint32_t so = (uint32_t)sc * STAGE_B;
        #pragma unroll
        for (int ks = 0; ks < 2; ++ks) {
            const uint32_t cByte = (uint32_t)(2 * ks + cl) << 4;
            const uint32_t cA = cByte ^ xA;
            const uint32_t cB = cByte ^ xB;
            uint32_t am[4][4], bb[2][4];

            // term 1: Ah x Bh
            #pragma unroll
            for (int mt = 0; mt < 4; mt++) ldsm4(am[mt], aBase + so + mt * 1024 + cA);
            #pragma unroll
            for (int p = 0; p < 2; p++)    ldsm4(bb[p], bBase + so + p * 1024 + cB);
            #pragma unroll
            for (int mt = 0; mt < 4; mt++)
                #pragma unroll
                for (int nt = 0; nt < 4; nt++)
                    mma_bf16(acc[mt][nt], am[mt],
                             bb[nt >> 1][nt & 1], bb[nt >> 1][2 + (nt & 1)]);

            // term 2: Ah x Bl  (bl reuses a small pool; ah still live)
            {
                uint32_t bl[2][4];
                #pragma unroll
                for (int p = 0; p < 2; p++)
                    ldsm4(bl[p], bBase + so + TILE_B + p * 1024 + cB);
                #pragma unroll
                for (int mt = 0; mt < 4; mt++)
                    #pragma unroll
                    for (int nt = 0; nt < 4; nt++)
                        mma_bf16(acc[mt][nt], am[mt],
                                 bl[nt >> 1][nt & 1], bl[nt >> 1][2 + (nt & 1)]);
            }

            // term 3: Al x Bh  (al overwrites ah registers — ah now dead)
            #pragma unroll
            for (int mt = 0; mt < 4; mt++)
                ldsm4(am[mt], aBase + so + TILE_B + mt * 1024 + cA);
            #pragma unroll
            for (int mt = 0; mt < 4; mt++)
                #pragma unroll
                for (int nt = 0; nt < 4; nt++)
                    mma_bf16(acc[mt][nt], am[mt],
                             bb[nt >> 1][nt & 1], bb[nt >> 1][2 + (nt & 1)]);
        }
        sc = (sc == 2) ? 0 : sc + 1;
    }

    // ---- Epilogue: bias + relu, direct global writes (no smem use) ----
    const int r0 = rowBase + warp_m * 64 + (lane >> 2);
    const int c0 = colBase + warp_n * 32 + (lane & 3) * 2;
    #pragma unroll
    for (int mt = 0; mt < 4; mt++) {
        #pragma unroll
        for (int nt = 0; nt < 4; nt++) {
            const int r = r0 + mt * 16;
            const int c = c0 + nt * 8;
            const float bv0 = __ldg(bias + c);
            const float bv1 = __ldg(bias + c + 1);
            float v00 = fmaxf(acc[mt][nt][0] + bv0, 0.0f);
            float v01 = fmaxf(acc[mt][nt][1] + bv1, 0.0f);
            float v10 = fmaxf(acc[mt][nt][2] + bv0, 0.0f);
            float v11 = fmaxf(acc[mt][nt][3] + bv1, 0.0f);
            if (MODE == 1) {
                #pragma unroll
                for (int rr = 0; rr < 2; rr++) {
                    float a = rr ? v10 : v00;
                    float b = rr ? v11 : v01;
                    __nv_bfloat16 h0 = __float2bfloat16(a);
                    __nv_bfloat16 l0 = __float2bfloat16(a - __bfloat162float(h0));
                    __nv_bfloat16 h1 = __float2bfloat16(b);
                    __nv_bfloat16 l1 = __float2bfloat16(b - __bfloat162float(h1));
                    __nv_bfloat16* rp = g_H3 + (size_t)(r + rr * 8) * 2 * DH + c;
                    *(__nv_bfloat162*)rp        = __nv_bfloat162(h0, h1);
                    *(__nv_bfloat162*)(rp + DH) = __nv_bfloat162(l0, l1);
                }
            } else {
                *(float2*)&g_h2[(size_t)r * DH + c]       = make_float2(v00, v01);
                *(float2*)&g_h2[(size_t)(r + 8) * DH + c] = make_float2(v10, v11);
            }
        }
    }
}

// ---------------------------------------------------------------------------
// Kernel 4: heads, 8 rows per block (amortize head-weight reads 8x).
// ---------------------------------------------------------------------------
#define XR 4104                       // padded row stride (conflict-free)
#define HEADS_SMEM ((8 * XR + N_HEAD * 8) * 4)

__global__ void __launch_bounds__(256)
heads8_kernel(const float* __restrict__ X,
              const float* __restrict__ Wc, const float* __restrict__ bc,
              const float* __restrict__ Wr, const float* __restrict__ br,
              float* __restrict__ out) {
    extern __shared__ float hs[];
    float* xs = hs;                   // [8][XR]
    float* hv = hs + 8 * XR;          // [N_HEAD][8]
    const int n0 = blockIdx.x * 8;
    const int tid = threadIdx.x;
    const int wid = tid >> 5, lane = tid & 31;

    for (int i = tid; i < 8 * DH; i += 256) {
        const int r = i >> 12, k = i & (DH - 1);
        xs[r * XR + k] = X[(size_t)(n0 + r) * DH + k];
    }
    __syncthreads();

    for (int o = wid; o < N_HEAD; o += 8) {
        const float* Wp;
        int ld;
        float bv;
        if (o < N_CLS) { Wp = Wc + o;           ld = N_CLS; bv = bc[o]; }
        else           { Wp = Wr + (o - N_CLS); ld = N_REG; bv = br[o - N_CLS]; }
        float a0=0,a1=0,a2=0,a3=0,a4=0,a5=0,a6=0,a7=0;
        for (int k = lane; k < DH; k += 32) {
            const float w = __ldg(Wp + (size_t)k * ld);
            a0 += xs[0*XR + k] * w;  a1 += xs[1*XR + k] * w;
            a2 += xs[2*XR + k] * w;  a3 += xs[3*XR + k] * w;
            a4 += xs[4*XR + k] * w;  a5 += xs[5*XR + k] * w;
            a6 += xs[6*XR + k] * w;  a7 += xs[7*XR + k] * w;
        }
        #pragma unroll
        for (int off = 16; off > 0; off >>= 1) {
            a0 += __shfl_down_sync(0xffffffffu, a0, off);
            a1 += __shfl_down_sync(0xffffffffu, a1, off);
            a2 += __shfl_down_sync(0xffffffffu, a2, off);
            a3 += __shfl_down_sync(0xffffffffu, a3, off);
            a4 += __shfl_down_sync(0xffffffffu, a4, off);
            a5 += __shfl_down_sync(0xffffffffu, a5, off);
            a6 += __shfl_down_sync(0xffffffffu, a6, off);
            a7 += __shfl_down_sync(0xffffffffu, a7, off);
        }
        if (lane == 0) {
            hv[o * 8 + 0] = a0 + bv;  hv[o * 8 + 1] = a1 + bv;
            hv[o * 8 + 2] = a2 + bv;  hv[o * 8 + 3] = a3 + bv;
            hv[o * 8 + 4] = a4 + bv;  hv[o * 8 + 5] = a5 + bv;
            hv[o * 8 + 6] = a6 + bv;  hv[o * 8 + 7] = a7 + bv;
        }
    }
    __syncthreads();

    if (tid < 8) {
        const int r = tid;
        float mx = hv[r];
        #pragma unroll
        for (int o = 1; o < N_CLS; o++) mx = fmaxf(mx, hv[o * 8 + r]);
        float s = 0.0f;
        float e[N_CLS];
        #pragma unroll
        for (int o = 0; o < N_CLS; o++) { e[o] = expf(hv[o * 8 + r] - mx); s += e[o]; }
        const float inv = 1.0f / s;
        #pragma unroll
        for (int o = 0; o < N_CLS; o++)
            out[(size_t)(n0 + r) * N_CLS + o] = e[o] * inv;
    }
    for (int i = tid; i < 8 * N_REG; i += 256) {
        const int r = i / N_REG, j = i - r * N_REG;
        out[(size_t)NPROP * N_CLS + (size_t)(n0 + r) * N_REG + j] = hv[(N_CLS + j) * 8 + r];
    }
}

// ---------------------------------------------------------------------------
extern "C" void kernel_launch(void* const* d_in, const int* in_sizes, int n_in,
                              void* d_out, int out_size) {
    const float* feats = (const float*)d_in[0];
    const float* props = (const float*)d_in[1];
    const float* W1    = (const float*)d_in[2];
    const float* b1    = (const float*)d_in[3];
    const float* W2    = (const float*)d_in[4];
    const float* b2    = (const float*)d_in[5];
    const float* Wc    = (const float*)d_in[6];
    const float* bc    = (const float*)d_in[7];
    const float* Wr    = (const float*)d_in[8];
    const float* br    = (const float*)d_in[9];
    float* out = (float*)d_out;

    __nv_bfloat16 *A3, *B1, *H3, *B2;
    float* h2;
    cudaGetSymbolAddress((void**)&A3, g_A3);
    cudaGetSymbolAddress((void**)&B1, g_B1);
    cudaGetSymbolAddress((void**)&H3, g_H3);
    cudaGetSymbolAddress((void**)&B2, g_B2);
    cudaGetSymbolAddress((void**)&h2, g_h2);

    cudaFuncSetAttribute(gemm_mma<1>, cudaFuncAttributeMaxDynamicSharedMemorySize, GEMM_SMEM);
    cudaFuncSetAttribute(gemm_mma<2>, cudaFuncAttributeMaxDynamicSharedMemorySize, GEMM_SMEM);
    cudaFuncSetAttribute(heads8_kernel, cudaFuncAttributeMaxDynamicSharedMemorySize, HEADS_SMEM);

    // 1) ROI align + maxpool + bf16 split (+ zero pad rows)
    roi_pool_kernel<<<MPAD, 256>>>(feats, props);

    // 2) weight transpose + split
    w_transpose_split<<<dim3(DH / 32, K1 / 32), dim3(32, 8)>>>(W1, B1, K1, DH);
    w_transpose_split<<<dim3(DH / 32, DH / 32), dim3(32, 8)>>>(W2, B2, DH, DH);

    // 3) FC1: [1024, K1] x [4096, K1]^T (3-term split), bias+relu, split out
    gemm_mma<1><<<dim3(DH / 128, MPAD / 128), 256, GEMM_SMEM>>>(A3, B1, b1, K1);

    // 4) FC2: [1024, DH] x [4096, DH]^T (3-term split), bias+relu, fp32 out
    gemm_mma<2><<<dim3(DH / 128, MPAD / 128), 256, GEMM_SMEM>>>(H3, B2, b2, DH);

    // 5) heads (8 rows per block)
    heads8_kernel<<<NPROP / 8, 256, HEADS_SMEM>>>(h2, Wc, bc, Wr, br, out);
}

// round 17
// speedup vs baseline: 3.0057x; 1.0234x over previous
#include <cuda_runtime.h>
#include <cuda_bf16.h>
#include <math.h>
#include <stdint.h>

#define H_F 38
#define W_F 50
#define C_F 512
#define CROP_SZ 14
#define ROI 7
#define NPROP 1000
#define MPAD 1024
#define K1 25088
#define DH 4096
#define N_CLS 21
#define N_REG 80
#define N_HEAD (N_CLS + N_REG)   // 101

// ---------------- scratch (static device globals; no allocation APIs) -------
// A-side layout per row: [hi(K) | lo(K)]  (row stride = 2K elements)
__device__ __nv_bfloat16 g_A3[(size_t)MPAD * 2 * K1];  // split pooled features
__device__ __nv_bfloat16 g_B1[(size_t)DH * 2 * K1];    // W1^T split
__device__ __nv_bfloat16 g_H3[(size_t)MPAD * 2 * DH];  // FC1 out split
__device__ __nv_bfloat16 g_B2[(size_t)DH * 2 * DH];    // W2^T split
__device__ float         g_h2[(size_t)MPAD * DH];      // FC2 out fp32

// ---------------- PTX helpers (plain sm_80+ features only) ------------------
__device__ __forceinline__ uint32_t smem_u32(const void* p) {
    uint32_t a;
    asm("{ .reg .u64 t; cvta.to.shared.u64 t, %1; cvt.u32.u64 %0, t; }"
        : "=r"(a) : "l"(p));
    return a;
}
__device__ __forceinline__ void cp16(uint32_t dst, const void* src) {
    asm volatile("cp.async.cg.shared.global [%0], [%1], 16;"
                 :: "r"(dst), "l"(src) : "memory");
}
__device__ __forceinline__ void ldsm4(uint32_t* r, uint32_t a) {
    asm volatile("ldmatrix.sync.aligned.m8n8.x4.shared.b16 {%0,%1,%2,%3}, [%4];"
                 : "=r"(r[0]), "=r"(r[1]), "=r"(r[2]), "=r"(r[3]) : "r"(a));
}
__device__ __forceinline__ void mma_bf16(float* c, const uint32_t* a,
                                         uint32_t b0, uint32_t b1) {
    asm volatile(
        "mma.sync.aligned.m16n8k16.row.col.f32.bf16.bf16.f32 "
        "{%0,%1,%2,%3}, {%4,%5,%6,%7}, {%8,%9}, {%0,%1,%2,%3};"
        : "+f"(c[0]), "+f"(c[1]), "+f"(c[2]), "+f"(c[3])
        : "r"(a[0]), "r"(a[1]), "r"(a[2]), "r"(a[3]), "r"(b0), "r"(b1));
}

// ---------------------------------------------------------------------------
// Fused prep kernel: roi+pool+split (blocks [0, MPAD)),
// W1 transpose+split (next 100352 blocks), W2 transpose+split (next 16384).
// All three are independent; fusing lets them overlap on the SM scheduler.
// ---------------------------------------------------------------------------
#define TR1_BX (DH / 32)          // 128
#define TR1_BY (K1 / 32)          // 784
#define TR1_BLOCKS (TR1_BX * TR1_BY)
#define TR2_BX (DH / 32)
#define TR2_BY (DH / 32)
#define TR2_BLOCKS (TR2_BX * TR2_BY)
#define PREP_BLOCKS (MPAD + TR1_BLOCKS + TR2_BLOCKS)

__device__ __forceinline__ void roi_part(int n,
                                         const float* __restrict__ feats,
                                         const float* __restrict__ props,
                                         int* sidx, float* sw) {
    const int tid = threadIdx.x;
    if (n >= NPROP) {  // zero pad rows (deterministic every launch)
        uint4 z = make_uint4(0u, 0u, 0u, 0u);
        uint4* row = (uint4*)(g_A3 + (size_t)n * 2 * K1);
        for (int i = tid; i < (2 * K1) / 8; i += 256) row[i] = z;
        return;
    }
    int* sy0 = sidx;               int* sy1 = sidx + CROP_SZ;
    int* sx0 = sidx + 2 * CROP_SZ; int* sx1 = sidx + 3 * CROP_SZ;
    float* swy = sw;               float* swx = sw + CROP_SZ;

    if (tid < CROP_SZ) {
        const float y1 = props[n * 4 + 0];
        const float y2 = props[n * 4 + 2];
        float ys = y1 * (float)(H_F - 1)
                 + (float)tid * ((y2 - y1) * (float)(H_F - 1) / (float)(CROP_SZ - 1));
        float y0f = floorf(ys);
        int y0 = min(max((int)y0f, 0), H_F - 1);
        sy0[tid] = y0;
        sy1[tid] = min(y0 + 1, H_F - 1);
        swy[tid] = ys - y0f;
    } else if (tid >= 32 && tid < 32 + CROP_SZ) {
        const int i = tid - 32;
        const float x1 = props[n * 4 + 1];
        const float x2 = props[n * 4 + 3];
        float xs = x1 * (float)(W_F - 1)
                 + (float)i * ((x2 - x1) * (float)(W_F - 1) / (float)(CROP_SZ - 1));
        float x0f = floorf(xs);
        int x0 = min(max((int)x0f, 0), W_F - 1);
        sx0[i] = x0;
        sx1[i] = min(x0 + 1, W_F - 1);
        swx[i] = xs - x0f;
    }
    __syncthreads();

    const size_t base = (size_t)n * 2 * K1;
    for (int idx = tid; idx < K1 / 4; idx += 256) {
        const int c4 = idx & 127;          // group of 4 channels
        const int p  = idx >> 7;           // 0..48 = ph*7+pw
        const int pw = p % ROI;
        const int ph = p / ROI;
        float4 m = make_float4(-1e30f, -1e30f, -1e30f, -1e30f);
        #pragma unroll
        for (int sy = 0; sy < 2; sy++) {
            const int iy = 2 * ph + sy;
            const int y0 = sy0[iy], y1i = sy1[iy];
            const float wy = swy[iy];
            #pragma unroll
            for (int sx = 0; sx < 2; sx++) {
                const int ix = 2 * pw + sx;
                const int x0 = sx0[ix], x1i = sx1[ix];
                const float wx = swx[ix];
                const float4 v00 = *(const float4*)(feats + (size_t)(y0  * W_F + x0 ) * C_F + c4 * 4);
                const float4 v01 = *(const float4*)(feats + (size_t)(y0  * W_F + x1i) * C_F + c4 * 4);
                const float4 v10 = *(const float4*)(feats + (size_t)(y1i * W_F + x0 ) * C_F + c4 * 4);
                const float4 v11 = *(const float4*)(feats + (size_t)(y1i * W_F + x1i) * C_F + c4 * 4);
                #pragma unroll
                for (int q = 0; q < 4; q++) {
                    const float a00 = ((const float*)&v00)[q];
                    const float a01 = ((const float*)&v01)[q];
                    const float a10 = ((const float*)&v10)[q];
                    const float a11 = ((const float*)&v11)[q];
                    const float top = a00 * (1.0f - wx) + a01 * wx;
                    const float bot = a10 * (1.0f - wx) + a11 * wx;
                    const float v   = top * (1.0f - wy) + bot * wy;
                    ((float*)&m)[q] = fmaxf(((float*)&m)[q], v);
                }
            }
        }
        const int out = p * C_F + c4 * 4;
        __nv_bfloat16 h[4], l[4];
        #pragma unroll
        for (int q = 0; q < 4; q++) {
            const float v = ((const float*)&m)[q];
            h[q] = __float2bfloat16(v);
            l[q] = __float2bfloat16(v - __bfloat162float(h[q]));
        }
        *(__nv_bfloat162*)(g_A3 + base + out)          = __nv_bfloat162(h[0], h[1]);
        *(__nv_bfloat162*)(g_A3 + base + out + 2)      = __nv_bfloat162(h[2], h[3]);
        *(__nv_bfloat162*)(g_A3 + base + K1 + out)     = __nv_bfloat162(l[0], l[1]);
        *(__nv_bfloat162*)(g_A3 + base + K1 + out + 2) = __nv_bfloat162(l[2], l[3]);
    }
}

__device__ __forceinline__ void trans_part(const float* __restrict__ W,
                                           __nv_bfloat16* __restrict__ B3,
                                           int K, int n0, int k0, float* t /*32x33*/) {
    const int tid = threadIdx.x;
    const int tx = tid & 31, ty = tid >> 5;   // 32 x 8
    #pragma unroll
    for (int i = 0; i < 4; i++) {
        int k = k0 + ty + i * 8;
        t[(ty + i * 8) * 33 + tx] = W[(size_t)k * DH + n0 + tx];
    }
    __syncthreads();
    #pragma unroll
    for (int i = 0; i < 4; i++) {
        int n = n0 + ty + i * 8;
        int k = k0 + tx;
        float v = t[tx * 33 + ty + i * 8];
        __nv_bfloat16 hi = __float2bfloat16(v);
        __nv_bfloat16 lo = __float2bfloat16(v - __bfloat162float(hi));
        size_t base = (size_t)n * 2 * (size_t)K;
        B3[base + k]     = hi;
        B3[base + K + k] = lo;
    }
}

__global__ void __launch_bounds__(256)
prep_kernel(const float* __restrict__ feats, const float* __restrict__ props,
            const float* __restrict__ W1, const float* __restrict__ W2) {
    __shared__ int   sidx[4 * CROP_SZ];
    __shared__ float sw[2 * CROP_SZ];
    __shared__ float tile[32 * 33];
    const int bid = blockIdx.x;
    if (bid < MPAD) {
        roi_part(bid, feats, props, sidx, sw);
    } else if (bid < MPAD + TR1_BLOCKS) {
        const int r = bid - MPAD;
        trans_part(W1, g_B1, K1, (r % TR1_BX) * 32, (r / TR1_BX) * 32, tile);
    } else {
        const int r = bid - MPAD - TR1_BLOCKS;
        trans_part(W2, g_B2, DH, (r % TR2_BX) * 32, (r / TR2_BX) * 32, tile);
    }
}

// ---------------------------------------------------------------------------
// GEMM: warp-level mma.sync bf16, 3-term split accumulation.
// BM=BN=128, BK=32. 3-stage cp.async pipeline, ONE syncthreads per chunk.
// Term order ah*bh -> ah*bl -> al*bh with register reuse => 128 regs, 2 CTA/SM.
// ---------------------------------------------------------------------------
#define TILE_B   8192
#define STAGE_B  32768
#define GEMM_SMEM (3 * STAGE_B)   // 98304

template <int MODE>
__global__ void __launch_bounds__(256, 2)
gemm_mma(const __nv_bfloat16* __restrict__ A, const __nv_bfloat16* __restrict__ B,
         const float* __restrict__ bias, int K) {
    extern __shared__ char smem[];
    const uint32_t sb = smem_u32(smem);
    const int tid = threadIdx.x;
    const int lane = tid & 31, wid = tid >> 5;
    const int warp_m = wid >> 2, warp_n = wid & 3;
    const int rowBase = blockIdx.y * 128, colBase = blockIdx.x * 128;
    const int nIter = K >> 5;

    // ---- global->smem mapping: thread = (row, 32B-half); swizzled dst ----
    const int lr = tid >> 1, lh = tid & 1;
    const size_t strideA = 2 * (size_t)K;
    const __nv_bfloat16* aSrc = A + (size_t)(rowBase + lr) * strideA + lh * 16;
    const __nv_bfloat16* bSrc = B + (size_t)(colBase + lr) * strideA + lh * 16;
    const uint32_t xw = (uint32_t)(lr & 3) << 4;
    const uint32_t d0off = (uint32_t)lr * 64 + (((uint32_t)(2 * lh)     << 4) ^ xw);
    const uint32_t d1off = (uint32_t)lr * 64 + (((uint32_t)(2 * lh + 1) << 4) ^ xw);

    auto issue = [&](int it, int slot) {
        const uint32_t d = sb + (uint32_t)slot * STAGE_B;
        const __nv_bfloat16* ap = aSrc + (size_t)it * 32;
        const __nv_bfloat16* bp = bSrc + (size_t)it * 32;
        cp16(d + d0off,              ap);          // Ah
        cp16(d + d1off,              ap + 8);
        cp16(d + TILE_B + d0off,     ap + K);      // Al
        cp16(d + TILE_B + d1off,     ap + K + 8);
        cp16(d + 2 * TILE_B + d0off, bp);          // Bh
        cp16(d + 2 * TILE_B + d1off, bp + 8);
        cp16(d + 3 * TILE_B + d0off, bp + K);      // Bl
        cp16(d + 3 * TILE_B + d1off, bp + K + 8);
        asm volatile("cp.async.commit_group;" ::: "memory");
    };

    float acc[4][4][4];
    #pragma unroll
    for (int i = 0; i < 4; i++)
        #pragma unroll
        for (int j = 0; j < 4; j++)
            #pragma unroll
            for (int q = 0; q < 4; q++) acc[i][j][q] = 0.0f;

    issue(0, 0);
    issue(1, 1);

    // ---- ldmatrix addressing (swizzled) ----
    const int rA = warp_m * 64 + (lane & 15);
    const int rB = warp_n * 32 + (lane & 15);
    const uint32_t xA = (uint32_t)(rA & 3) << 4;
    const uint32_t xB = (uint32_t)(rB & 3) << 4;
    const uint32_t aBase = sb + (uint32_t)rA * 64;
    const uint32_t bBase = sb + 2 * TILE_B + (uint32_t)rB * 64;
    const uint32_t cl = (uint32_t)(lane >> 4);   // 0/1: which 16B chunk of the k16

    int sp = 2;   // next issue slot
    int sc = 0;   // current compute slot

    for (int it = 0; it < nIter; ++it) {
        if (it + 1 < nIter) {
            asm volatile("cp.async.wait_group 1;" ::: "memory");
        } else {
            asm volatile("cp.async.wait_group 0;" ::: "memory");
        }
        __syncthreads();

        if (it + 2 < nIter) {
            issue(it + 2, sp);
            sp = (sp == 2) ? 0 : sp + 1;
        }

        const uint32_t so = (uint32_t)sc * STAGE_B;
        #pragma unroll
        for (int ks = 0; ks < 2; ++ks) {
            const uint32_t cByte = (uint32_t)(2 * ks + cl) << 4;
            const uint32_t cA = cByte ^ xA;
            const uint32_t cB = cByte ^ xB;
            uint32_t am[4][4], bb[2][4];

            // term 1: Ah x Bh
            #pragma unroll
            for (int mt = 0; mt < 4; mt++) ldsm4(am[mt], aBase + so + mt * 1024 + cA);
            #pragma unroll
            for (int p = 0; p < 2; p++)    ldsm4(bb[p], bBase + so + p * 1024 + cB);
            #pragma unroll
            for (int mt = 0; mt < 4; mt++)
                #pragma unroll
                for (int nt = 0; nt < 4; nt++)
                    mma_bf16(acc[mt][nt], am[mt],
                             bb[nt >> 1][nt & 1], bb[nt >> 1][2 + (nt & 1)]);

            // term 2: Ah x Bl  (bl reuses a small pool; ah still live)
            {
                uint32_t bl[2][4];
                #pragma unroll
                for (int p = 0; p < 2; p++)
                    ldsm4(bl[p], bBase + so + TILE_B + p * 1024 + cB);
                #pragma unroll
                for (int mt = 0; mt < 4; mt++)
                    #pragma unroll
                    for (int nt = 0; nt < 4; nt++)
                        mma_bf16(acc[mt][nt], am[mt],
                                 bl[nt >> 1][nt & 1], bl[nt >> 1][2 + (nt & 1)]);
            }

            // term 3: Al x Bh  (al overwrites ah registers — ah now dead)
            #pragma unroll
            for (int mt = 0; mt < 4; mt++)
                ldsm4(am[mt], aBase + so + TILE_B + mt * 1024 + cA);
            #pragma unroll
            for (int mt = 0; mt < 4; mt++)
                #pragma unroll
                for (int nt = 0; nt < 4; nt++)
                    mma_bf16(acc[mt][nt], am[mt],
                             bb[nt >> 1][nt & 1], bb[nt >> 1][2 + (nt & 1)]);
        }
        sc = (sc == 2) ? 0 : sc + 1;
    }

    // ---- Epilogue: bias + relu, direct global writes (no smem use) ----
    const int r0 = rowBase + warp_m * 64 + (lane >> 2);
    const int c0 = colBase + warp_n * 32 + (lane & 3) * 2;
    #pragma unroll
    for (int mt = 0; mt < 4; mt++) {
        #pragma unroll
        for (int nt = 0; nt < 4; nt++) {
            const int r = r0 + mt * 16;
            const int c = c0 + nt * 8;
            const float bv0 = __ldg(bias + c);
            const float bv1 = __ldg(bias + c + 1);
            float v00 = fmaxf(acc[mt][nt][0] + bv0, 0.0f);
            float v01 = fmaxf(acc[mt][nt][1] + bv1, 0.0f);
            float v10 = fmaxf(acc[mt][nt][2] + bv0, 0.0f);
            float v11 = fmaxf(acc[mt][nt][3] + bv1, 0.0f);
            if (MODE == 1) {
                #pragma unroll
                for (int rr = 0; rr < 2; rr++) {
                    float a = rr ? v10 : v00;
                    float b = rr ? v11 : v01;
                    __nv_bfloat16 h0 = __float2bfloat16(a);
                    __nv_bfloat16 l0 = __float2bfloat16(a - __bfloat162float(h0));
                    __nv_bfloat16 h1 = __float2bfloat16(b);
                    __nv_bfloat16 l1 = __float2bfloat16(b - __bfloat162float(h1));
                    __nv_bfloat16* rp = g_H3 + (size_t)(r + rr * 8) * 2 * DH + c;
                    *(__nv_bfloat162*)rp        = __nv_bfloat162(h0, h1);
                    *(__nv_bfloat162*)(rp + DH) = __nv_bfloat162(l0, l1);
                }
            } else {
                *(float2*)&g_h2[(size_t)r * DH + c]       = make_float2(v00, v01);
                *(float2*)&g_h2[(size_t)(r + 8) * DH + c] = make_float2(v10, v11);
            }
        }
    }
}

// ---------------------------------------------------------------------------
// heads, 8 rows per block (amortize head-weight reads 8x).
// ---------------------------------------------------------------------------
#define XR 4104                       // padded row stride (conflict-free)
#define HEADS_SMEM ((8 * XR + N_HEAD * 8) * 4)

__global__ void __launch_bounds__(256)
heads8_kernel(const float* __restrict__ X,
              const float* __restrict__ Wc, const float* __restrict__ bc,
              const float* __restrict__ Wr, const float* __restrict__ br,
              float* __restrict__ out) {
    extern __shared__ float hs[];
    float* xs = hs;                   // [8][XR]
    float* hv = hs + 8 * XR;          // [N_HEAD][8]
    const int n0 = blockIdx.x * 8;
    const int tid = threadIdx.x;
    const int wid = tid >> 5, lane = tid & 31;

    for (int i = tid; i < 8 * DH; i += 256) {
        const int r = i >> 12, k = i & (DH - 1);
        xs[r * XR + k] = X[(size_t)(n0 + r) * DH + k];
    }
    __syncthreads();

    for (int o = wid; o < N_HEAD; o += 8) {
        const float* Wp;
        int ld;
        float bv;
        if (o < N_CLS) { Wp = Wc + o;           ld = N_CLS; bv = bc[o]; }
        else           { Wp = Wr + (o - N_CLS); ld = N_REG; bv = br[o - N_CLS]; }
        float a0=0,a1=0,a2=0,a3=0,a4=0,a5=0,a6=0,a7=0;
        for (int k = lane; k < DH; k += 32) {
            const float w = __ldg(Wp + (size_t)k * ld);
            a0 += xs[0*XR + k] * w;  a1 += xs[1*XR + k] * w;
            a2 += xs[2*XR + k] * w;  a3 += xs[3*XR + k] * w;
            a4 += xs[4*XR + k] * w;  a5 += xs[5*XR + k] * w;
            a6 += xs[6*XR + k] * w;  a7 += xs[7*XR + k] * w;
        }
        #pragma unroll
        for (int off = 16; off > 0; off >>= 1) {
            a0 += __shfl_down_sync(0xffffffffu, a0, off);
            a1 += __shfl_down_sync(0xffffffffu, a1, off);
            a2 += __shfl_down_sync(0xffffffffu, a2, off);
            a3 += __shfl_down_sync(0xffffffffu, a3, off);
            a4 += __shfl_down_sync(0xffffffffu, a4, off);
            a5 += __shfl_down_sync(0xffffffffu, a5, off);
            a6 += __shfl_down_sync(0xffffffffu, a6, off);
            a7 += __shfl_down_sync(0xffffffffu, a7, off);
        }
        if (lane == 0) {
            hv[o * 8 + 0] = a0 + bv;  hv[o * 8 + 1] = a1 + bv;
            hv[o * 8 + 2] = a2 + bv;  hv[o * 8 + 3] = a3 + bv;
            hv[o * 8 + 4] = a4 + bv;  hv[o * 8 + 5] = a5 + bv;
            hv[o * 8 + 6] = a6 + bv;  hv[o * 8 + 7] = a7 + bv;
        }
    }
    __syncthreads();

    if (tid < 8) {
        const int r = tid;
        float mx = hv[r];
        #pragma unroll
        for (int o = 1; o < N_CLS; o++) mx = fmaxf(mx, hv[o * 8 + r]);
        float s = 0.0f;
        float e[N_CLS];
        #pragma unroll
        for (int o = 0; o < N_CLS; o++) { e[o] = expf(hv[o * 8 + r] - mx); s += e[o]; }
        const float inv = 1.0f / s;
        #pragma unroll
        for (int o = 0; o < N_CLS; o++)
            out[(size_t)(n0 + r) * N_CLS + o] = e[o] * inv;
    }
    for (int i = tid; i < 8 * N_REG; i += 256) {
        const int r = i / N_REG, j = i - r * N_REG;
        out[(size_t)NPROP * N_CLS + (size_t)(n0 + r) * N_REG + j] = hv[(N_CLS + j) * 8 + r];
    }
}

// ---------------------------------------------------------------------------
extern "C" void kernel_launch(void* const* d_in, const int* in_sizes, int n_in,
                              void* d_out, int out_size) {
    const float* feats = (const float*)d_in[0];
    const float* props = (const float*)d_in[1];
    const float* W1    = (const float*)d_in[2];
    const float* b1    = (const float*)d_in[3];
    const float* W2    = (const float*)d_in[4];
    const float* b2    = (const float*)d_in[5];
    const float* Wc    = (const float*)d_in[6];
    const float* bc    = (const float*)d_in[7];
    const float* Wr    = (const float*)d_in[8];
    const float* br    = (const float*)d_in[9];
    float* out = (float*)d_out;

    __nv_bfloat16 *A3, *H3;
    float* h2;
    cudaGetSymbolAddress((void**)&A3, g_A3);
    cudaGetSymbolAddress((void**)&H3, g_H3);
    cudaGetSymbolAddress((void**)&h2, g_h2);
    __nv_bfloat16 *B1, *B2;
    cudaGetSymbolAddress((void**)&B1, g_B1);
    cudaGetSymbolAddress((void**)&B2, g_B2);

    cudaFuncSetAttribute(gemm_mma<1>, cudaFuncAttributeMaxDynamicSharedMemorySize, GEMM_SMEM);
    cudaFuncSetAttribute(gemm_mma<2>, cudaFuncAttributeMaxDynamicSharedMemorySize, GEMM_SMEM);
    cudaFuncSetAttribute(heads8_kernel, cudaFuncAttributeMaxDynamicSharedMemorySize, HEADS_SMEM);

    // 1) fused prep: roi+pool+split  ||  W1 transpose+split  ||  W2 transpose+split
    prep_kernel<<<PREP_BLOCKS, 256>>>(feats, props, W1, W2);

    // 2) FC1: [1024, K1] x [4096, K1]^T (3-term split), bias+relu, split out
    gemm_mma<1><<<dim3(DH / 128, MPAD / 128), 256, GEMM_SMEM>>>(A3, B1, b1, K1);

    // 3) FC2: [1024, DH] x [4096, DH]^T (3-term split), bias+relu, fp32 out
    gemm_mma<2><<<dim3(DH / 128, MPAD / 128), 256, GEMM_SMEM>>>(H3, B2, b2, DH);

    // 4) heads (8 rows per block)
    heads8_kernel<<<NPROP / 8, 256, HEADS_SMEM>>>(h2, Wc, bc, Wr, br, out);
}